// round 16
// baseline (speedup 1.0000x reference)
#include <cuda_runtime.h>
#include <cuda_bf16.h>
#include <mma.h>
#include <math.h>
#include <cstdint>

using namespace nvcuda;

#define N_NODES 50000
#define N_PAD   50048          // padded row count (multiple of 64)
#define N_EDGES 800000
#define DIM     128
#define N_LAYERS 4
#define BN_EPS  1e-5f
#define SCAN_B  49             // ceil(50000/1024)

// ---------------- scratch (device globals; no allocations allowed) ----------
__device__ int    g_deg[N_NODES];
__device__ int    g_rowptr[N_NODES + 1];
__device__ int    g_cursor[N_NODES];
__device__ int    g_bsum[64];
__device__ unsigned g_arrive;          // scan arrival counter (reset by count_kernel)
__device__ int2   g_edge[N_EDGES];     // (src, coef bits) in CSR order
__device__ float  g_dis[N_NODES];
__device__ float  g_h[(size_t)N_PAD * DIM];   // padded: WMMA stores full tiles
__device__ float  g_y[(size_t)N_NODES * DIM];
__device__ double g_stats[2 * DIM];    // [0:128) sum, [128:256) sumsq (self-zeroing)
__device__ float  g_affine[2 * DIM];   // [0:128) scale, [128:256) shift
// W as bf16 hi/lo, row-major [k][n], per layer
__device__ __nv_bfloat16 g_wh[N_LAYERS][DIM * DIM];
__device__ __nv_bfloat16 g_wl[N_LAYERS][DIM * DIM];

// ---------------- CSR count (also resets scan arrival counter) --------------
__global__ void count_kernel(const int* __restrict__ dst) {
    int e = blockIdx.x * blockDim.x + threadIdx.x;
    if (e == 0) g_arrive = 0u;
    if (e < N_EDGES) atomicAdd(&g_deg[dst[e]], 1);
}

// fused multi-block scan: in-block scan -> post bsum -> spin until all 49
// blocks posted (all co-resident: 49 < 148 SMs) -> finalize from registers.
__global__ void __launch_bounds__(1024) scan_kernel() {
    __shared__ int wsum[32];
    __shared__ int boff_s;
    int b = blockIdx.x, tid = threadIdx.x;
    int lane = tid & 31, wid = tid >> 5;
    int i = b * 1024 + tid;
    int v = (i < N_NODES) ? g_deg[i] : 0;
    int x = v;
    #pragma unroll
    for (int o = 1; o < 32; o <<= 1) {
        int t = __shfl_up_sync(0xffffffffu, x, o);
        if (lane >= o) x += t;
    }
    if (lane == 31) wsum[wid] = x;
    __syncthreads();
    if (wid == 0) {
        int w = wsum[lane];
        #pragma unroll
        for (int o = 1; o < 32; o <<= 1) {
            int t = __shfl_up_sync(0xffffffffu, w, o);
            if (lane >= o) w += t;
        }
        wsum[lane] = w;
    }
    __syncthreads();
    int incl = x + (wid > 0 ? wsum[wid - 1] : 0);   // in-block inclusive (register)

    // ---- post this block's sum, then grid-wide arrival spin ----
    if (tid == 1023) g_bsum[b] = incl;
    __threadfence();
    __syncthreads();
    if (tid == 0) {
        atomicAdd(&g_arrive, 1u);
        while (*((volatile unsigned*)&g_arrive) < (unsigned)SCAN_B) { }
    }
    __syncthreads();
    __threadfence();

    // ---- redundant 64-thread scan of the 49 block sums (warps 0-1) ----
    if (wid < 2) {
        __shared__ int sh2[2];
        int bv = (tid < SCAN_B) ? g_bsum[tid] : 0;
        int bx = bv;
        #pragma unroll
        for (int o = 1; o < 32; o <<= 1) {
            int t = __shfl_up_sync(0xffffffffu, bx, o);
            if (lane >= o) bx += t;
        }
        if (lane == 31) sh2[wid] = bx;
        __syncthreads();
        int bincl = bx + (wid > 0 ? sh2[0] : 0);
        if (tid == b) boff_s = bincl - bv;          // exclusive offset for block b
    } else {
        __syncthreads();
    }
    __syncthreads();

    // ---- finalize from register-held inclusive value ----
    if (i < N_NODES) {
        int gincl = incl + boff_s;
        g_rowptr[i + 1] = gincl;
        g_cursor[i]     = gincl - v;
        g_dis[i]        = rsqrtf((float)v + 1.0f);
        g_deg[i]        = 0;
    }
    if (b == 0 && tid == 0) g_rowptr[0] = 0;
}

__global__ void scatter_kernel(const int* __restrict__ src, const int* __restrict__ dst) {
    int e = blockIdx.x * blockDim.x + threadIdx.x;
    if (e < N_EDGES) {
        int d = dst[e];
        int s = src[e];
        int p = atomicAdd(&g_cursor[d], 1);
        float c = g_dis[s] * g_dis[d];
        g_edge[p] = make_int2(s, __float_as_int(c));
    }
}

// ---------------- W prep: fp32 [k][n] -> bf16 hi (trunc) + lo (residual) ----
__global__ void wprep_kernel(const float* __restrict__ Ws) {
    int idx = blockIdx.x * blockDim.x + threadIdx.x;
    if (idx >= N_LAYERS * DIM * DIM) return;
    int l = idx >> 14;
    int r = idx & (DIM * DIM - 1);
    float w = Ws[(size_t)l * DIM * DIM + r];
    uint32_t wi = __float_as_uint(w);
    float hi = __uint_as_float(wi & 0xffff0000u);     // truncated bf16
    g_wh[l][r] = __float2bfloat16_rz(hi);
    g_wl[l][r] = __float2bfloat16_rn(w - hi);
}

// ---------------- GEMM: H = affine(Z) @ W via WMMA bf16 split ----------------
// CTA: 64 rows x 128 cols, 256 threads (8 warps, each 32 rows x 32 cols).
// K chunked by 64 through smem. 53 KB smem -> 3-4 CTAs/SM (24-32 warps).
#define BM   64
#define A_LD 72      // bf16 elems per A smem row (64 rows)
#define B_LD 136     // bf16 elems per B smem row (64 rows)
#define SM_AH 0
#define SM_AL (64 * A_LD)
#define SM_BH (2 * 64 * A_LD)
#define SM_BL (2 * 64 * A_LD + 64 * B_LD)
#define GEMM_SMEM_ELEMS (2 * 64 * A_LD + 2 * 64 * B_LD)
#define GEMM_SMEM_BYTES (GEMM_SMEM_ELEMS * 2)    // 53248 B

__global__ void __launch_bounds__(256) gemm_kernel(const float* __restrict__ Z,
                                                   int layer,
                                                   float* __restrict__ H,
                                                   int apply_affine) {
    extern __shared__ __nv_bfloat16 smem[];
    int tid  = threadIdx.x;
    int wid  = tid >> 5;
    int row0 = blockIdx.x * BM;
    int warp_m = wid >> 2;           // 0..1 -> rows warp_m*32
    int warp_n = wid & 3;            // 0..3 -> cols warp_n*32

    wmma::fragment<wmma::accumulator, 16, 16, 16, float> acc[2][2];
    #pragma unroll
    for (int i = 0; i < 2; i++)
        #pragma unroll
        for (int j = 0; j < 2; j++) wmma::fill_fragment(acc[i][j], 0.0f);

    const __nv_bfloat16* wh = g_wh[layer];
    const __nv_bfloat16* wl = g_wl[layer];

    for (int kc = 0; kc < DIM; kc += 64) {
        // ---- stage B chunk: 64 k-rows x 128 n-cols (hi+lo) = 4096 uint32 each ----
        {
            const uint32_t* wh32 = (const uint32_t*)wh;
            const uint32_t* wl32 = (const uint32_t*)wl;
            uint32_t* bh32 = (uint32_t*)(smem + SM_BH);
            uint32_t* bl32 = (uint32_t*)(smem + SM_BL);
            #pragma unroll
            for (int i = 0; i < 16; i++) {
                int idx = tid + i * 256;        // 0..4095
                int r = idx >> 6;               // k-row 0..63
                int c = idx & 63;               // uint32 col (2 bf16)
                bh32[r * (B_LD / 2) + c] = wh32[(size_t)(kc + r) * 64 + c];
                bl32[r * (B_LD / 2) + c] = wl32[(size_t)(kc + r) * 64 + c];
            }
        }
        // ---- stage A chunk: 64 rows x 64 k, affine + bf16 split ----
        {
            int row = tid >> 2;                 // 0..63
            int qq  = tid & 3;                  // covers 4 float4 each
            int grow = row0 + row;
            uint32_t* ah32 = (uint32_t*)(smem + SM_AH) + row * (A_LD / 2);
            uint32_t* al32 = (uint32_t*)(smem + SM_AL) + row * (A_LD / 2);
            #pragma unroll
            for (int q = 0; q < 4; q++) {
                int k4 = qq * 4 + q;            // float4 index within chunk, 0..15
                float4 v = (grow < N_NODES)
                         ? ((const float4*)Z)[(size_t)grow * 32 + (kc >> 2) + k4]
                         : make_float4(0.f, 0.f, 0.f, 0.f);
                if (apply_affine) {
                    float4 sc = ((const float4*)g_affine)[(kc >> 2) + k4];
                    float4 sh = ((const float4*)g_affine)[32 + (kc >> 2) + k4];
                    v.x = fmaf(v.x, sc.x, sh.x);
                    v.y = fmaf(v.y, sc.y, sh.y);
                    v.z = fmaf(v.z, sc.z, sh.z);
                    v.w = fmaf(v.w, sc.w, sh.w);
                }
                float vv[4] = {v.x, v.y, v.z, v.w};
                #pragma unroll
                for (int p = 0; p < 2; p++) {
                    uint32_t b0 = __float_as_uint(vv[2 * p]);
                    uint32_t b1 = __float_as_uint(vv[2 * p + 1]);
                    uint32_t hi = __byte_perm(b0, b1, 0x7632);
                    float r0 = vv[2 * p]     - __uint_as_float(b0 & 0xffff0000u);
                    float r1 = vv[2 * p + 1] - __uint_as_float(b1 & 0xffff0000u);
                    __nv_bfloat162 lo2 = __float22bfloat162_rn(make_float2(r0, r1));
                    ah32[k4 * 2 + p] = hi;
                    al32[k4 * 2 + p] = *(uint32_t*)&lo2;
                }
            }
        }
        __syncthreads();

        // ---- 4 k-steps of 16 ----
        #pragma unroll
        for (int ks = 0; ks < 4; ks++) {
            wmma::fragment<wmma::matrix_a, 16, 16, 16, __nv_bfloat16, wmma::row_major> a_hi[2], a_lo[2];
            #pragma unroll
            for (int i = 0; i < 2; i++) {
                const __nv_bfloat16* ap = smem + SM_AH +
                    (warp_m * 32 + i * 16) * A_LD + ks * 16;
                const __nv_bfloat16* alp = smem + SM_AL +
                    (warp_m * 32 + i * 16) * A_LD + ks * 16;
                wmma::load_matrix_sync(a_hi[i], ap, A_LD);
                wmma::load_matrix_sync(a_lo[i], alp, A_LD);
            }
            #pragma unroll
            for (int j = 0; j < 2; j++) {
                wmma::fragment<wmma::matrix_b, 16, 16, 16, __nv_bfloat16, wmma::row_major> b_hi, b_lo;
                const __nv_bfloat16* bp = smem + SM_BH +
                    (ks * 16) * B_LD + warp_n * 32 + j * 16;
                const __nv_bfloat16* blp = smem + SM_BL +
                    (ks * 16) * B_LD + warp_n * 32 + j * 16;
                wmma::load_matrix_sync(b_hi, bp, B_LD);
                wmma::load_matrix_sync(b_lo, blp, B_LD);
                #pragma unroll
                for (int i = 0; i < 2; i++) {
                    wmma::mma_sync(acc[i][j], a_hi[i], b_hi, acc[i][j]);
                    wmma::mma_sync(acc[i][j], a_hi[i], b_lo, acc[i][j]);
                    wmma::mma_sync(acc[i][j], a_lo[i], b_hi, acc[i][j]);
                }
            }
        }
        __syncthreads();
    }

    // ---- store 32x32 per warp (H is row-padded; unconditional tile stores) ----
    #pragma unroll
    for (int i = 0; i < 2; i++) {
        #pragma unroll
        for (int j = 0; j < 2; j++) {
            int row = row0 + warp_m * 32 + i * 16;
            int col = warp_n * 32 + j * 16;
            wmma::store_matrix_sync(H + (size_t)row * DIM + col, acc[i][j],
                                    DIM, wmma::mem_row_major);
        }
    }
}

// ---------------- Aggregation + bias + ReLU + BN-stat accumulation ----------
// one warp per dst row (grid-stride); lane owns cols lane*4..lane*4+3
// edges consumed 2-at-a-time via int4 (alignment-peeled, single induction var)
__global__ void __launch_bounds__(256) agg_kernel(const float* __restrict__ bvec) {
    __shared__ float red[8 * 256];

    int lane = threadIdx.x & 31;
    int wid  = threadIdx.x >> 5;
    int gw   = blockIdx.x * 8 + wid;
    int nw   = gridDim.x * 8;

    float4 bb = ((const float4*)bvec)[lane];

    float s0 = 0.f, s1 = 0.f, s2 = 0.f, s3 = 0.f;
    float q0 = 0.f, q1 = 0.f, q2 = 0.f, q3 = 0.f;

    const float4* h4 = (const float4*)g_h;

    for (int r = gw; r < N_NODES; r += nw) {
        float dr = g_dis[r];
        float4 hv = h4[(size_t)r * 32 + lane];
        float cself = dr * dr;
        float4 acc;
        acc.x = hv.x * cself; acc.y = hv.y * cself;
        acc.z = hv.z * cself; acc.w = hv.w * cself;

        int j   = g_rowptr[r];
        int end = g_rowptr[r + 1];

        if ((j & 1) && j < end) {          // peel to 16B alignment
            int2 e = __ldg(&g_edge[j]);
            float c = __int_as_float(e.y);
            float4 hs = h4[(size_t)e.x * 32 + lane];
            acc.x = fmaf(c, hs.x, acc.x); acc.y = fmaf(c, hs.y, acc.y);
            acc.z = fmaf(c, hs.z, acc.z); acc.w = fmaf(c, hs.w, acc.w);
            j++;
        }
        int np = (end - j) >> 1;           // int4 pairs
        const int4* ep = (const int4*)(g_edge + j);
        for (int p = 0; p < np; p++) {
            int4 e2 = __ldg(&ep[p]);
            float ca = __int_as_float(e2.y);
            float cb = __int_as_float(e2.w);
            float4 ha = h4[(size_t)e2.x * 32 + lane];
            float4 hb = h4[(size_t)e2.z * 32 + lane];
            acc.x = fmaf(ca, ha.x, acc.x); acc.y = fmaf(ca, ha.y, acc.y);
            acc.z = fmaf(ca, ha.z, acc.z); acc.w = fmaf(ca, ha.w, acc.w);
            acc.x = fmaf(cb, hb.x, acc.x); acc.y = fmaf(cb, hb.y, acc.y);
            acc.z = fmaf(cb, hb.z, acc.z); acc.w = fmaf(cb, hb.w, acc.w);
        }
        j += np * 2;
        if (j < end) {                     // tail edge
            int2 e = __ldg(&g_edge[j]);
            float c = __int_as_float(e.y);
            float4 hs = h4[(size_t)e.x * 32 + lane];
            acc.x = fmaf(c, hs.x, acc.x); acc.y = fmaf(c, hs.y, acc.y);
            acc.z = fmaf(c, hs.z, acc.z); acc.w = fmaf(c, hs.w, acc.w);
        }

        acc.x = fmaxf(acc.x + bb.x, 0.f);
        acc.y = fmaxf(acc.y + bb.y, 0.f);
        acc.z = fmaxf(acc.z + bb.z, 0.f);
        acc.w = fmaxf(acc.w + bb.w, 0.f);
        ((float4*)g_y)[(size_t)r * 32 + lane] = acc;

        s0 += acc.x; s1 += acc.y; s2 += acc.z; s3 += acc.w;
        q0 = fmaf(acc.x, acc.x, q0); q1 = fmaf(acc.y, acc.y, q1);
        q2 = fmaf(acc.z, acc.z, q2); q3 = fmaf(acc.w, acc.w, q3);
    }

    float* rw = &red[wid * 256 + lane * 8];
    rw[0] = s0; rw[1] = s1; rw[2] = s2; rw[3] = s3;
    rw[4] = q0; rw[5] = q1; rw[6] = q2; rw[7] = q3;
    __syncthreads();

    int tid = threadIdx.x;
    float a = 0.f;
    #pragma unroll
    for (int w = 0; w < 8; w++) a += red[w * 256 + tid];
    int l = tid >> 3, j2 = tid & 7;
    int col = l * 4 + (j2 & 3);
    atomicAdd(&g_stats[(j2 >> 2) * 128 + col], (double)a);
}

// ---------------- BN finalize (self-zeroing stats) ---------------------------
__global__ void stats_kernel(const float* __restrict__ gamma,
                             const float* __restrict__ beta) {
    int c = threadIdx.x;
    double s = g_stats[c];
    double q = g_stats[128 + c];
    g_stats[c] = 0.0;
    g_stats[128 + c] = 0.0;
    double mu  = s * (1.0 / N_NODES);
    double var = q * (1.0 / N_NODES) - mu * mu;
    float scale = gamma[c] * rsqrtf((float)var + BN_EPS);
    g_affine[c]       = scale;
    g_affine[128 + c] = beta[c] - (float)mu * scale;
}

// ---------------- final normalize --------------------------------------------
__global__ void __launch_bounds__(256) norm_kernel(float* __restrict__ out) {
    int idx = blockIdx.x * blockDim.x + threadIdx.x;
    if (idx < N_NODES * 32) {
        int c4 = idx & 31;
        float4 v  = ((const float4*)g_y)[idx];
        float4 sc = ((const float4*)g_affine)[c4];
        float4 sh = ((const float4*)(g_affine + 128))[c4];
        v.x = fmaf(v.x, sc.x, sh.x);
        v.y = fmaf(v.y, sc.y, sh.y);
        v.z = fmaf(v.z, sc.z, sh.z);
        v.w = fmaf(v.w, sc.w, sh.w);
        ((float4*)out)[idx] = v;
    }
}

// ---------------- launch -----------------------------------------------------
extern "C" void kernel_launch(void* const* d_in, const int* in_sizes, int n_in,
                              void* d_out, int out_size) {
    const float* x      = (const float*)d_in[0];
    const int*   ei     = (const int*)d_in[1];
    const float* Ws     = (const float*)d_in[2];
    const float* bs     = (const float*)d_in[3];
    const float* gammas = (const float*)d_in[4];
    const float* betas  = (const float*)d_in[5];
    const int* src = ei;
    const int* dst = ei + N_EDGES;

    void *p_h, *p_y;
    cudaGetSymbolAddress(&p_h, g_h);
    cudaGetSymbolAddress(&p_y, g_y);

    cudaFuncSetAttribute(gemm_kernel, cudaFuncAttributeMaxDynamicSharedMemorySize,
                         GEMM_SMEM_BYTES);

    // one-time stream/event creation (resource setup only; identical work every call)
    static cudaStream_t s2 = nullptr;
    static cudaEvent_t ev_fork = nullptr, ev_join = nullptr;
    if (s2 == nullptr) {
        cudaStreamCreateWithFlags(&s2, cudaStreamNonBlocking);
        cudaEventCreateWithFlags(&ev_fork, cudaEventDisableTiming);
        cudaEventCreateWithFlags(&ev_join, cudaEventDisableTiming);
    }

    // fork: stream s2 runs wprep + layer-0 GEMM (independent of CSR build)
    cudaEventRecord(ev_fork, 0);
    cudaStreamWaitEvent(s2, ev_fork, 0);
    wprep_kernel<<<(N_LAYERS * DIM * DIM + 255) / 256, 256, 0, s2>>>(Ws);
    gemm_kernel<<<N_PAD / BM, 256, GEMM_SMEM_BYTES, s2>>>(x, 0, (float*)p_h, 0);
    cudaEventRecord(ev_join, s2);

    // main stream: CSR build (scan fully fused, one kernel)
    count_kernel<<<(N_EDGES + 255) / 256, 256>>>(dst);
    scan_kernel<<<SCAN_B, 1024>>>();
    scatter_kernel<<<(N_EDGES + 255) / 256, 256>>>(src, dst);

    // join: agg layer 0 needs both CSR and layer-0 H
    cudaStreamWaitEvent(0, ev_join, 0);

    for (int l = 0; l < N_LAYERS; l++) {
        if (l > 0) {
            gemm_kernel<<<N_PAD / BM, 256, GEMM_SMEM_BYTES>>>(
                (const float*)p_y, l, (float*)p_h, 1);
        }
        agg_kernel<<<1184, 256>>>(bs + l * DIM);
        stats_kernel<<<1, 128>>>(gammas + l * DIM, betas + l * DIM);
    }
    norm_kernel<<<(N_NODES * 32 + 255) / 256, 256>>>((float*)d_out);
}

// round 17
// speedup vs baseline: 1.0349x; 1.0349x over previous
#include <cuda_runtime.h>
#include <cuda_bf16.h>
#include <mma.h>
#include <math.h>
#include <cstdint>

using namespace nvcuda;

#define N_NODES 50000
#define N_PAD   50048          // padded row count (multiple of 64)
#define N_EDGES 800000
#define DIM     128
#define N_LAYERS 4
#define BN_EPS  1e-5f
#define SCAN_B  49             // ceil(50000/1024)
#define AGG_BLOCKS 592         // 4 CTAs/SM x 148 SMs = exactly one resident wave

// ---------------- scratch (device globals; no allocations allowed) ----------
__device__ int    g_deg[N_NODES];
__device__ int    g_rowptr[N_NODES + 1];
__device__ int    g_cursor[N_NODES];
__device__ int    g_bsum[64];
__device__ int2   g_edge[N_EDGES];     // (src, coef bits) in CSR order
__device__ float  g_dis[N_NODES];
__device__ float  g_h[(size_t)N_PAD * DIM];   // padded: WMMA stores full tiles
__device__ float  g_y[(size_t)N_NODES * DIM];
__device__ double g_stats[2 * DIM];    // [0:128) sum, [128:256) sumsq (self-zeroing)
__device__ float  g_affine[2 * DIM];   // [0:128) scale, [128:256) shift
// W as bf16 hi/lo, row-major [k][n], per layer
__device__ __nv_bfloat16 g_wh[N_LAYERS][DIM * DIM];
__device__ __nv_bfloat16 g_wl[N_LAYERS][DIM * DIM];

// ---------------- CSR build ------------------------------------------------
__global__ void count_kernel(const int* __restrict__ dst) {
    int e = blockIdx.x * blockDim.x + threadIdx.x;
    if (e < N_EDGES) atomicAdd(&g_deg[dst[e]], 1);
}

// multi-block scan, stage 1: in-block inclusive scan of degrees
__global__ void __launch_bounds__(1024) scan1_kernel() {
    __shared__ int wsum[32];
    int b = blockIdx.x, tid = threadIdx.x;
    int lane = tid & 31, wid = tid >> 5;
    int i = b * 1024 + tid;
    int v = (i < N_NODES) ? g_deg[i] : 0;
    int x = v;
    #pragma unroll
    for (int o = 1; o < 32; o <<= 1) {
        int t = __shfl_up_sync(0xffffffffu, x, o);
        if (lane >= o) x += t;
    }
    if (lane == 31) wsum[wid] = x;
    __syncthreads();
    if (wid == 0) {
        int w = wsum[lane];
        #pragma unroll
        for (int o = 1; o < 32; o <<= 1) {
            int t = __shfl_up_sync(0xffffffffu, w, o);
            if (lane >= o) w += t;
        }
        wsum[lane] = w;
    }
    __syncthreads();
    int incl = x + (wid > 0 ? wsum[wid - 1] : 0);
    if (i < N_NODES) g_cursor[i] = incl;   // temp: in-block inclusive
    if (tid == 1023) g_bsum[b] = incl;
}

// stage 2+3 fused: each block scans the 49 block sums itself (first 2 warps),
// then finalizes rowptr/cursor/dis and zeros deg.
__global__ void __launch_bounds__(1024) scan3_kernel() {
    __shared__ int boff_s;                 // this block's exclusive offset
    int b = blockIdx.x, tid = threadIdx.x;
    int lane = tid & 31, wid = tid >> 5;

    if (wid < 2) {                         // redundant 64-thread scan of g_bsum
        __shared__ int sh2[2];
        int v = (tid < SCAN_B) ? g_bsum[tid] : 0;
        int x = v;
        #pragma unroll
        for (int o = 1; o < 32; o <<= 1) {
            int t = __shfl_up_sync(0xffffffffu, x, o);
            if (lane >= o) x += t;
        }
        if (lane == 31) sh2[wid] = x;
        __syncwarp();
        __syncthreads();
        int incl = x + (wid > 0 ? sh2[0] : 0);
        if (tid == b) boff_s = incl - v;   // exclusive offset for block b
    } else {
        __syncthreads();
    }
    __syncthreads();

    int i = b * 1024 + tid;
    if (i < N_NODES) {
        int v    = g_deg[i];
        int incl = g_cursor[i] + boff_s;
        g_rowptr[i + 1] = incl;
        g_cursor[i]     = incl - v;
        g_dis[i]        = rsqrtf((float)v + 1.0f);
        g_deg[i]        = 0;
    }
    if (b == 0 && tid == 0) g_rowptr[0] = 0;
}

__global__ void scatter_kernel(const int* __restrict__ src, const int* __restrict__ dst) {
    int e = blockIdx.x * blockDim.x + threadIdx.x;
    if (e < N_EDGES) {
        int d = dst[e];
        int s = src[e];
        int p = atomicAdd(&g_cursor[d], 1);
        float c = g_dis[s] * g_dis[d];
        g_edge[p] = make_int2(s, __float_as_int(c));
    }
}

// ---------------- W prep: fp32 [k][n] -> bf16 hi (trunc) + lo (residual) ----
__global__ void wprep_kernel(const float* __restrict__ Ws) {
    int idx = blockIdx.x * blockDim.x + threadIdx.x;
    if (idx >= N_LAYERS * DIM * DIM) return;
    int l = idx >> 14;
    int r = idx & (DIM * DIM - 1);
    float w = Ws[(size_t)l * DIM * DIM + r];
    uint32_t wi = __float_as_uint(w);
    float hi = __uint_as_float(wi & 0xffff0000u);     // truncated bf16
    g_wh[l][r] = __float2bfloat16_rz(hi);
    g_wl[l][r] = __float2bfloat16_rn(w - hi);
}

// ---------------- GEMM: H = affine(Z) @ W via WMMA bf16 split ----------------
// CTA: 64 rows x 128 cols, 256 threads (8 warps, each 32 rows x 32 cols).
// K chunked by 64 through smem. 53 KB smem -> 3-4 CTAs/SM (24-32 warps).
#define BM   64
#define A_LD 72      // bf16 elems per A smem row (64 rows)
#define B_LD 136     // bf16 elems per B smem row (64 rows)
#define SM_AH 0
#define SM_AL (64 * A_LD)
#define SM_BH (2 * 64 * A_LD)
#define SM_BL (2 * 64 * A_LD + 64 * B_LD)
#define GEMM_SMEM_ELEMS (2 * 64 * A_LD + 2 * 64 * B_LD)
#define GEMM_SMEM_BYTES (GEMM_SMEM_ELEMS * 2)    // 53248 B

__global__ void __launch_bounds__(256) gemm_kernel(const float* __restrict__ Z,
                                                   int layer,
                                                   float* __restrict__ H,
                                                   int apply_affine) {
    extern __shared__ __nv_bfloat16 smem[];
    int tid  = threadIdx.x;
    int wid  = tid >> 5;
    int row0 = blockIdx.x * BM;
    int warp_m = wid >> 2;           // 0..1 -> rows warp_m*32
    int warp_n = wid & 3;            // 0..3 -> cols warp_n*32

    wmma::fragment<wmma::accumulator, 16, 16, 16, float> acc[2][2];
    #pragma unroll
    for (int i = 0; i < 2; i++)
        #pragma unroll
        for (int j = 0; j < 2; j++) wmma::fill_fragment(acc[i][j], 0.0f);

    const __nv_bfloat16* wh = g_wh[layer];
    const __nv_bfloat16* wl = g_wl[layer];

    for (int kc = 0; kc < DIM; kc += 64) {
        // ---- stage B chunk: 64 k-rows x 128 n-cols (hi+lo) = 4096 uint32 each ----
        {
            const uint32_t* wh32 = (const uint32_t*)wh;
            const uint32_t* wl32 = (const uint32_t*)wl;
            uint32_t* bh32 = (uint32_t*)(smem + SM_BH);
            uint32_t* bl32 = (uint32_t*)(smem + SM_BL);
            #pragma unroll
            for (int i = 0; i < 16; i++) {
                int idx = tid + i * 256;        // 0..4095
                int r = idx >> 6;               // k-row 0..63
                int c = idx & 63;               // uint32 col (2 bf16)
                bh32[r * (B_LD / 2) + c] = wh32[(size_t)(kc + r) * 64 + c];
                bl32[r * (B_LD / 2) + c] = wl32[(size_t)(kc + r) * 64 + c];
            }
        }
        // ---- stage A chunk: 64 rows x 64 k, affine + bf16 split ----
        {
            int row = tid >> 2;                 // 0..63
            int qq  = tid & 3;                  // covers 4 float4 each
            int grow = row0 + row;
            uint32_t* ah32 = (uint32_t*)(smem + SM_AH) + row * (A_LD / 2);
            uint32_t* al32 = (uint32_t*)(smem + SM_AL) + row * (A_LD / 2);
            #pragma unroll
            for (int q = 0; q < 4; q++) {
                int k4 = qq * 4 + q;            // float4 index within chunk, 0..15
                float4 v = (grow < N_NODES)
                         ? ((const float4*)Z)[(size_t)grow * 32 + (kc >> 2) + k4]
                         : make_float4(0.f, 0.f, 0.f, 0.f);
                if (apply_affine) {
                    float4 sc = ((const float4*)g_affine)[(kc >> 2) + k4];
                    float4 sh = ((const float4*)g_affine)[32 + (kc >> 2) + k4];
                    v.x = fmaf(v.x, sc.x, sh.x);
                    v.y = fmaf(v.y, sc.y, sh.y);
                    v.z = fmaf(v.z, sc.z, sh.z);
                    v.w = fmaf(v.w, sc.w, sh.w);
                }
                float vv[4] = {v.x, v.y, v.z, v.w};
                #pragma unroll
                for (int p = 0; p < 2; p++) {
                    uint32_t b0 = __float_as_uint(vv[2 * p]);
                    uint32_t b1 = __float_as_uint(vv[2 * p + 1]);
                    uint32_t hi = __byte_perm(b0, b1, 0x7632);
                    float r0 = vv[2 * p]     - __uint_as_float(b0 & 0xffff0000u);
                    float r1 = vv[2 * p + 1] - __uint_as_float(b1 & 0xffff0000u);
                    __nv_bfloat162 lo2 = __float22bfloat162_rn(make_float2(r0, r1));
                    ah32[k4 * 2 + p] = hi;
                    al32[k4 * 2 + p] = *(uint32_t*)&lo2;
                }
            }
        }
        __syncthreads();

        // ---- 4 k-steps of 16 ----
        #pragma unroll
        for (int ks = 0; ks < 4; ks++) {
            wmma::fragment<wmma::matrix_a, 16, 16, 16, __nv_bfloat16, wmma::row_major> a_hi[2], a_lo[2];
            #pragma unroll
            for (int i = 0; i < 2; i++) {
                const __nv_bfloat16* ap = smem + SM_AH +
                    (warp_m * 32 + i * 16) * A_LD + ks * 16;
                const __nv_bfloat16* alp = smem + SM_AL +
                    (warp_m * 32 + i * 16) * A_LD + ks * 16;
                wmma::load_matrix_sync(a_hi[i], ap, A_LD);
                wmma::load_matrix_sync(a_lo[i], alp, A_LD);
            }
            #pragma unroll
            for (int j = 0; j < 2; j++) {
                wmma::fragment<wmma::matrix_b, 16, 16, 16, __nv_bfloat16, wmma::row_major> b_hi, b_lo;
                const __nv_bfloat16* bp = smem + SM_BH +
                    (ks * 16) * B_LD + warp_n * 32 + j * 16;
                const __nv_bfloat16* blp = smem + SM_BL +
                    (ks * 16) * B_LD + warp_n * 32 + j * 16;
                wmma::load_matrix_sync(b_hi, bp, B_LD);
                wmma::load_matrix_sync(b_lo, blp, B_LD);
                #pragma unroll
                for (int i = 0; i < 2; i++) {
                    wmma::mma_sync(acc[i][j], a_hi[i], b_hi, acc[i][j]);
                    wmma::mma_sync(acc[i][j], a_hi[i], b_lo, acc[i][j]);
                    wmma::mma_sync(acc[i][j], a_lo[i], b_hi, acc[i][j]);
                }
            }
        }
        __syncthreads();
    }

    // ---- store 32x32 per warp (H is row-padded; unconditional tile stores) ----
    #pragma unroll
    for (int i = 0; i < 2; i++) {
        #pragma unroll
        for (int j = 0; j < 2; j++) {
            int row = row0 + warp_m * 32 + i * 16;
            int col = warp_n * 32 + j * 16;
            wmma::store_matrix_sync(H + (size_t)row * DIM + col, acc[i][j],
                                    DIM, wmma::mem_row_major);
        }
    }
}

// ---------------- Aggregation + bias + ReLU + BN-stat accumulation ----------
// one warp per dst row (grid-stride); lane owns cols lane*4..lane*4+3
// edges consumed 2-at-a-time via int4 (alignment-peeled, single induction var)
__global__ void __launch_bounds__(256) agg_kernel(const float* __restrict__ bvec) {
    __shared__ float red[8 * 256];

    int lane = threadIdx.x & 31;
    int wid  = threadIdx.x >> 5;
    int gw   = blockIdx.x * 8 + wid;
    int nw   = gridDim.x * 8;

    float4 bb = ((const float4*)bvec)[lane];

    float s0 = 0.f, s1 = 0.f, s2 = 0.f, s3 = 0.f;
    float q0 = 0.f, q1 = 0.f, q2 = 0.f, q3 = 0.f;

    const float4* h4 = (const float4*)g_h;

    for (int r = gw; r < N_NODES; r += nw) {
        float dr = g_dis[r];
        float4 hv = h4[(size_t)r * 32 + lane];
        float cself = dr * dr;
        float4 acc;
        acc.x = hv.x * cself; acc.y = hv.y * cself;
        acc.z = hv.z * cself; acc.w = hv.w * cself;

        int j   = g_rowptr[r];
        int end = g_rowptr[r + 1];

        if ((j & 1) && j < end) {          // peel to 16B alignment
            int2 e = __ldg(&g_edge[j]);
            float c = __int_as_float(e.y);
            float4 hs = h4[(size_t)e.x * 32 + lane];
            acc.x = fmaf(c, hs.x, acc.x); acc.y = fmaf(c, hs.y, acc.y);
            acc.z = fmaf(c, hs.z, acc.z); acc.w = fmaf(c, hs.w, acc.w);
            j++;
        }
        int np = (end - j) >> 1;           // int4 pairs
        const int4* ep = (const int4*)(g_edge + j);
        for (int p = 0; p < np; p++) {
            int4 e2 = __ldg(&ep[p]);
            float ca = __int_as_float(e2.y);
            float cb = __int_as_float(e2.w);
            float4 ha = h4[(size_t)e2.x * 32 + lane];
            float4 hb = h4[(size_t)e2.z * 32 + lane];
            acc.x = fmaf(ca, ha.x, acc.x); acc.y = fmaf(ca, ha.y, acc.y);
            acc.z = fmaf(ca, ha.z, acc.z); acc.w = fmaf(ca, ha.w, acc.w);
            acc.x = fmaf(cb, hb.x, acc.x); acc.y = fmaf(cb, hb.y, acc.y);
            acc.z = fmaf(cb, hb.z, acc.z); acc.w = fmaf(cb, hb.w, acc.w);
        }
        j += np * 2;
        if (j < end) {                     // tail edge
            int2 e = __ldg(&g_edge[j]);
            float c = __int_as_float(e.y);
            float4 hs = h4[(size_t)e.x * 32 + lane];
            acc.x = fmaf(c, hs.x, acc.x); acc.y = fmaf(c, hs.y, acc.y);
            acc.z = fmaf(c, hs.z, acc.z); acc.w = fmaf(c, hs.w, acc.w);
        }

        acc.x = fmaxf(acc.x + bb.x, 0.f);
        acc.y = fmaxf(acc.y + bb.y, 0.f);
        acc.z = fmaxf(acc.z + bb.z, 0.f);
        acc.w = fmaxf(acc.w + bb.w, 0.f);
        ((float4*)g_y)[(size_t)r * 32 + lane] = acc;

        s0 += acc.x; s1 += acc.y; s2 += acc.z; s3 += acc.w;
        q0 = fmaf(acc.x, acc.x, q0); q1 = fmaf(acc.y, acc.y, q1);
        q2 = fmaf(acc.z, acc.z, q2); q3 = fmaf(acc.w, acc.w, q3);
    }

    float* rw = &red[wid * 256 + lane * 8];
    rw[0] = s0; rw[1] = s1; rw[2] = s2; rw[3] = s3;
    rw[4] = q0; rw[5] = q1; rw[6] = q2; rw[7] = q3;
    __syncthreads();

    int tid = threadIdx.x;
    float a = 0.f;
    #pragma unroll
    for (int w = 0; w < 8; w++) a += red[w * 256 + tid];
    int l = tid >> 3, j2 = tid & 7;
    int col = l * 4 + (j2 & 3);
    atomicAdd(&g_stats[(j2 >> 2) * 128 + col], (double)a);
}

// ---------------- BN finalize (self-zeroing stats) ---------------------------
__global__ void stats_kernel(const float* __restrict__ gamma,
                             const float* __restrict__ beta) {
    int c = threadIdx.x;
    double s = g_stats[c];
    double q = g_stats[128 + c];
    g_stats[c] = 0.0;
    g_stats[128 + c] = 0.0;
    double mu  = s * (1.0 / N_NODES);
    double var = q * (1.0 / N_NODES) - mu * mu;
    float scale = gamma[c] * rsqrtf((float)var + BN_EPS);
    g_affine[c]       = scale;
    g_affine[128 + c] = beta[c] - (float)mu * scale;
}

// ---------------- final normalize --------------------------------------------
__global__ void __launch_bounds__(256) norm_kernel(float* __restrict__ out) {
    int idx = blockIdx.x * blockDim.x + threadIdx.x;
    if (idx < N_NODES * 32) {
        int c4 = idx & 31;
        float4 v  = ((const float4*)g_y)[idx];
        float4 sc = ((const float4*)g_affine)[c4];
        float4 sh = ((const float4*)(g_affine + 128))[c4];
        v.x = fmaf(v.x, sc.x, sh.x);
        v.y = fmaf(v.y, sc.y, sh.y);
        v.z = fmaf(v.z, sc.z, sh.z);
        v.w = fmaf(v.w, sc.w, sh.w);
        ((float4*)out)[idx] = v;
    }
}

// ---------------- launch -----------------------------------------------------
extern "C" void kernel_launch(void* const* d_in, const int* in_sizes, int n_in,
                              void* d_out, int out_size) {
    const float* x      = (const float*)d_in[0];
    const int*   ei     = (const int*)d_in[1];
    const float* Ws     = (const float*)d_in[2];
    const float* bs     = (const float*)d_in[3];
    const float* gammas = (const float*)d_in[4];
    const float* betas  = (const float*)d_in[5];
    const int* src = ei;
    const int* dst = ei + N_EDGES;

    void *p_h, *p_y;
    cudaGetSymbolAddress(&p_h, g_h);
    cudaGetSymbolAddress(&p_y, g_y);

    cudaFuncSetAttribute(gemm_kernel, cudaFuncAttributeMaxDynamicSharedMemorySize,
                         GEMM_SMEM_BYTES);

    // one-time stream/event creation (resource setup only; identical work every call)
    static cudaStream_t s2 = nullptr;
    static cudaEvent_t ev_fork = nullptr, ev_join = nullptr;
    if (s2 == nullptr) {
        cudaStreamCreateWithFlags(&s2, cudaStreamNonBlocking);
        cudaEventCreateWithFlags(&ev_fork, cudaEventDisableTiming);
        cudaEventCreateWithFlags(&ev_join, cudaEventDisableTiming);
    }

    // fork: stream s2 runs wprep + layer-0 GEMM (independent of CSR build)
    cudaEventRecord(ev_fork, 0);
    cudaStreamWaitEvent(s2, ev_fork, 0);
    wprep_kernel<<<(N_LAYERS * DIM * DIM + 255) / 256, 256, 0, s2>>>(Ws);
    gemm_kernel<<<N_PAD / BM, 256, GEMM_SMEM_BYTES, s2>>>(x, 0, (float*)p_h, 0);
    cudaEventRecord(ev_join, s2);

    // main stream: CSR build (scan2 fused into scan3)
    count_kernel<<<(N_EDGES + 255) / 256, 256>>>(dst);
    scan1_kernel<<<SCAN_B, 1024>>>();
    scan3_kernel<<<SCAN_B, 1024>>>();
    scatter_kernel<<<(N_EDGES + 255) / 256, 256>>>(src, dst);

    // join: agg layer 0 needs both CSR and layer-0 H
    cudaStreamWaitEvent(0, ev_join, 0);

    for (int l = 0; l < N_LAYERS; l++) {
        if (l > 0) {
            gemm_kernel<<<N_PAD / BM, 256, GEMM_SMEM_BYTES>>>(
                (const float*)p_y, l, (float*)p_h, 1);
        }
        agg_kernel<<<AGG_BLOCKS, 256>>>(bs + l * DIM);
        stats_kernel<<<1, 128>>>(gammas + l * DIM, betas + l * DIM);
    }
    norm_kernel<<<(N_NODES * 32 + 255) / 256, 256>>>((float*)d_out);
}